// round 1
// baseline (speedup 1.0000x reference)
#include <cuda_runtime.h>
#include <math.h>

#define Bb 8
#define Cc 256
#define Nn 4096
#define Dd 32
#define Rr 32

// ---- scratch (__device__ globals: allowed; no runtime allocation) ----
__device__ float g_q[Bb * Nn * Dd];                 // [b][n][d]   4 MB
__device__ float g_k[Bb * Dd * Nn];                 // [b][d][n]   4 MB
__device__ float g_v[(size_t)Bb * Cc * Nn];         // [b][c][n]  32 MB
__device__ float g_attn[(size_t)Bb * Nn * Nn];      // [b][m][n] 512 MB
__device__ float g_stats[Bb * 2 * Cc];              // [b][mean(256),std(256)]
__device__ float g_coef[Bb * Cc];                   // 1 + lamb*sigmoid(...)

// ============================================================
// Kernel 1: q[b,n,d] = sum_c Wq[d,c] x[b,c,n] + bq[d] ; same for k
// block = (n-tile of 128, b), 128 threads (one per n)
// ============================================================
__global__ void qk_kernel(const float* __restrict__ x,
                          const float* __restrict__ Wq, const float* __restrict__ bq,
                          const float* __restrict__ Wk, const float* __restrict__ bk) {
    __shared__ float sWq[128][33];   // [c][d], padded vs 32-way bank conflict
    __shared__ float sWk[128][33];
    const int tid = threadIdx.x;
    const int b = blockIdx.y;
    const int n = blockIdx.x * 128 + tid;

    float accq[Dd], acck[Dd];
#pragma unroll
    for (int d = 0; d < Dd; d++) { accq[d] = bq[d]; acck[d] = bk[d]; }

    const float* xb = x + (size_t)b * Cc * Nn + n;

    for (int c0 = 0; c0 < Cc; c0 += 128) {
        __syncthreads();
        // load W chunk transposed: coalesced gmem (c fastest)
        for (int i = tid; i < 128 * Dd; i += 128) {
            int d = i >> 7;          // 0..31
            int c = i & 127;         // 0..127
            sWq[c][d] = Wq[d * Cc + c0 + c];
            sWk[c][d] = Wk[d * Cc + c0 + c];
        }
        __syncthreads();
        for (int cc = 0; cc < 128; cc++) {
            float xv = xb[(size_t)(c0 + cc) * Nn];
#pragma unroll
            for (int d = 0; d < Dd; d++) {
                accq[d] = fmaf(sWq[cc][d], xv, accq[d]);
                acck[d] = fmaf(sWk[cc][d], xv, acck[d]);
            }
        }
    }
    // write q [b][n][d]
    float* qo = g_q + ((size_t)b * Nn + n) * Dd;
#pragma unroll
    for (int d = 0; d < Dd; d += 4)
        *(float4*)(qo + d) = make_float4(accq[d], accq[d + 1], accq[d + 2], accq[d + 3]);
    // write k [b][d][n]
    float* ko = g_k + (size_t)b * Dd * Nn + n;
#pragma unroll
    for (int d = 0; d < Dd; d++) ko[(size_t)d * Nn] = acck[d];
}

// ============================================================
// Kernel 2: v[b,c,n] = sum_c' Wv[c,c'] x[b,c',n] + bv[c]
// block = (n-tile 128, c-tile 64, b), 128 threads (one per n), 64 acc each
// ============================================================
__global__ void vproj_kernel(const float* __restrict__ x,
                             const float* __restrict__ Wv, const float* __restrict__ bv) {
    __shared__ float sWv[64][65];    // [c'][c] padded
    const int tid = threadIdx.x;
    const int b = blockIdx.z;
    const int c0 = blockIdx.y * 64;
    const int n = blockIdx.x * 128 + tid;

    float acc[64];
#pragma unroll
    for (int i = 0; i < 64; i++) acc[i] = bv[c0 + i];

    const float* xb = x + (size_t)b * Cc * Nn + n;

    for (int cp0 = 0; cp0 < Cc; cp0 += 64) {
        __syncthreads();
        // Wv[(c0+i)][cp0+j] -> sWv[j][i] ; gmem coalesced along j
        for (int t = tid; t < 64 * 64; t += 128) {
            int i = t >> 6;      // c index
            int j = t & 63;      // c' index
            sWv[j][i] = Wv[(c0 + i) * Cc + cp0 + j];
        }
        __syncthreads();
        for (int j = 0; j < 64; j++) {
            float xv = xb[(size_t)(cp0 + j) * Nn];
#pragma unroll
            for (int i = 0; i < 64; i++) acc[i] = fmaf(sWv[j][i], xv, acc[i]);
        }
    }
    float* vo = g_v + ((size_t)b * Cc + c0) * Nn + n;
#pragma unroll
    for (int i = 0; i < 64; i++) vo[(size_t)i * Nn] = acc[i];
}

// ============================================================
// Kernel 3: S[b,m,n] = sum_d q[b,m,d] k[b,d,n]   (K = 32, one step)
// block tile 64m x 128n, 256 threads, 4x8 microtile
// ============================================================
__global__ void score_kernel() {
    __shared__ float sq[64][Dd];     // [m][d]  8 KB
    __shared__ float sk[Dd][128];    // [d][n] 16 KB
    const int tid = threadIdx.x;
    const int b = blockIdx.z;
    const int m0 = blockIdx.y * 64;
    const int n0 = blockIdx.x * 128;

    for (int i = tid; i < 64 * Dd; i += 256) {
        int m = i >> 5, d = i & 31;
        sq[m][d] = g_q[((size_t)b * Nn + m0 + m) * Dd + d];
    }
    for (int i = tid; i < Dd * 128; i += 256) {
        int d = i >> 7, n = i & 127;
        sk[d][n] = g_k[(size_t)b * Dd * Nn + (size_t)d * Nn + n0 + n];
    }
    __syncthreads();

    const int tx = tid & 15;   // n groups of 8
    const int ty = tid >> 4;   // m groups of 4
    float acc[4][8];
#pragma unroll
    for (int i = 0; i < 4; i++)
#pragma unroll
        for (int j = 0; j < 8; j++) acc[i][j] = 0.f;

#pragma unroll
    for (int d = 0; d < Dd; d++) {
        float qv[4];
#pragma unroll
        for (int i = 0; i < 4; i++) qv[i] = sq[ty * 4 + i][d];
        float kv[8];
        *(float4*)&kv[0] = *(const float4*)&sk[d][tx * 8];
        *(float4*)&kv[4] = *(const float4*)&sk[d][tx * 8 + 4];
#pragma unroll
        for (int i = 0; i < 4; i++)
#pragma unroll
            for (int j = 0; j < 8; j++) acc[i][j] = fmaf(qv[i], kv[j], acc[i][j]);
    }
#pragma unroll
    for (int i = 0; i < 4; i++) {
        float* o = g_attn + (size_t)b * Nn * Nn + (size_t)(m0 + ty * 4 + i) * Nn + n0 + tx * 8;
        *(float4*)&o[0] = make_float4(acc[i][0], acc[i][1], acc[i][2], acc[i][3]);
        *(float4*)&o[4] = make_float4(acc[i][4], acc[i][5], acc[i][6], acc[i][7]);
    }
}

// ============================================================
// Kernel 4: row softmax over n, one block per (b*Nn + m)
// ============================================================
__global__ void softmax_kernel() {
    __shared__ float buf[Nn];        // 16 KB
    __shared__ float red[8];
    const int tid = threadIdx.x;
    const int lane = tid & 31, warp = tid >> 5;
    float* row = g_attn + (size_t)blockIdx.x * Nn;

    float m = -1e30f;
    for (int i = tid; i < Nn; i += 256) {
        float v = row[i];
        buf[i] = v;
        m = fmaxf(m, v);
    }
#pragma unroll
    for (int o = 16; o; o >>= 1) m = fmaxf(m, __shfl_xor_sync(0xffffffffu, m, o));
    if (lane == 0) red[warp] = m;
    __syncthreads();
    if (tid < 32) {
        float v = (tid < 8) ? red[tid] : -1e30f;
#pragma unroll
        for (int o = 4; o; o >>= 1) v = fmaxf(v, __shfl_xor_sync(0xffffffffu, v, o));
        if (tid == 0) red[0] = v;
    }
    __syncthreads();
    const float gmax = red[0];
    __syncthreads();

    float s = 0.f;
    for (int i = tid; i < Nn; i += 256) {
        float e = __expf(buf[i] - gmax);
        buf[i] = e;
        s += e;
    }
#pragma unroll
    for (int o = 16; o; o >>= 1) s += __shfl_xor_sync(0xffffffffu, s, o);
    if (lane == 0) red[warp] = s;
    __syncthreads();
    if (tid < 32) {
        float v = (tid < 8) ? red[tid] : 0.f;
#pragma unroll
        for (int o = 4; o; o >>= 1) v += __shfl_xor_sync(0xffffffffu, v, o);
        if (tid == 0) red[0] = v;
    }
    __syncthreads();
    const float inv = 1.f / red[0];
    for (int i = tid; i < Nn; i += 256) row[i] = buf[i] * inv;
}

// ============================================================
// Kernel 5: per-(b,c) mean + unbiased std over N
// ============================================================
__global__ void stats_kernel(const float* __restrict__ x) {
    __shared__ float rs[8], rq[8];
    const int tid = threadIdx.x;
    const int lane = tid & 31, warp = tid >> 5;
    const float* p = x + (size_t)blockIdx.x * Nn;   // blockIdx.x = b*Cc + c

    float s = 0.f, sq = 0.f;
    for (int i = tid; i < Nn; i += 256) {
        float v = p[i];
        s += v;
        sq = fmaf(v, v, sq);
    }
#pragma unroll
    for (int o = 16; o; o >>= 1) {
        s += __shfl_xor_sync(0xffffffffu, s, o);
        sq += __shfl_xor_sync(0xffffffffu, sq, o);
    }
    if (lane == 0) { rs[warp] = s; rq[warp] = sq; }
    __syncthreads();
    if (tid == 0) {
        float ts = 0.f, tq = 0.f;
#pragma unroll
        for (int w = 0; w < 8; w++) { ts += rs[w]; tq += rq[w]; }
        float mean = ts / (float)Nn;
        float var = (tq - (float)Nn * mean * mean) / (float)(Nn - 1);
        float sd = sqrtf(fmaxf(var, 0.f));
        int b = blockIdx.x >> 8;      // /Cc
        int c = blockIdx.x & 255;
        g_stats[b * 2 * Cc + c] = mean;
        g_stats[b * 2 * Cc + Cc + c] = sd;
    }
}

// ============================================================
// Kernel 6: SE MLP -> coef[b,c] = 1 + lamb * sigmoid(relu(inp W1^T) W2^T)
// one block per b
// ============================================================
__global__ void mlp_kernel(const float* __restrict__ W1, const float* __restrict__ W2,
                           const float* __restrict__ lamb) {
    __shared__ float inp[2 * Cc];
    __shared__ float hid[Rr];
    const int tid = threadIdx.x;
    const int lane = tid & 31, warp = tid >> 5;
    const int b = blockIdx.x;

    for (int i = tid; i < 2 * Cc; i += 256) inp[i] = g_stats[b * 2 * Cc + i];
    __syncthreads();

#pragma unroll
    for (int t = 0; t < 4; t++) {
        int r = warp + 8 * t;
        float p = 0.f;
        for (int j = lane; j < 2 * Cc; j += 32) p = fmaf(inp[j], W1[r * 2 * Cc + j], p);
#pragma unroll
        for (int o = 16; o; o >>= 1) p += __shfl_xor_sync(0xffffffffu, p, o);
        if (lane == 0) hid[r] = fmaxf(p, 0.f);
    }
    __syncthreads();

    int c = tid;  // 256 threads == Cc
    float s = 0.f;
#pragma unroll
    for (int r = 0; r < Rr; r++) s = fmaf(hid[r], W2[c * Rr + r], s);
    float a = 1.f / (1.f + __expf(-s));
    g_coef[b * Cc + c] = 1.f + lamb[0] * a;
}

// ============================================================
// Kernel 7: out[b,c,m] = gamma * sum_n v[b,c,n] attn[b,m,n] + coef[b,c] * x[b,c,m]
// NT SGEMM 128x128 tile, BK=16, 256 threads, 8x8 microtile
// ============================================================
__global__ void __launch_bounds__(256) pv_kernel(const float* __restrict__ x,
                                                 const float* __restrict__ gamma,
                                                 float* __restrict__ out) {
    __shared__ float As[16][128];    // [k][c]
    __shared__ float Bs[16][128];    // [k][m]
    const int tid = threadIdx.x;
    const int tx = tid & 15;         // m groups
    const int ty = tid >> 4;         // c groups
    const int b = blockIdx.z;
    const int c0 = blockIdx.y * 128;
    const int m0 = blockIdx.x * 128;

    const float* A = g_v + (size_t)b * Cc * Nn;        // A[c][k] = v
    const float* Bm = g_attn + (size_t)b * Nn * Nn;    // B[m][k] = attn

    float acc[8][8];
#pragma unroll
    for (int i = 0; i < 8; i++)
#pragma unroll
        for (int j = 0; j < 8; j++) acc[i][j] = 0.f;

    for (int k0 = 0; k0 < Nn; k0 += 16) {
#pragma unroll
        for (int r = 0; r < 2; r++) {
            int fi = tid + r * 256;        // [0,512)
            int cc = fi >> 2;              // row within tile (0..127)
            int kg = fi & 3;               // float4 group within the 16-wide k slab
            float4 av = *(const float4*)(A + (size_t)(c0 + cc) * Nn + k0 + kg * 4);
            As[kg * 4 + 0][cc] = av.x; As[kg * 4 + 1][cc] = av.y;
            As[kg * 4 + 2][cc] = av.z; As[kg * 4 + 3][cc] = av.w;
            float4 bv = *(const float4*)(Bm + (size_t)(m0 + cc) * Nn + k0 + kg * 4);
            Bs[kg * 4 + 0][cc] = bv.x; Bs[kg * 4 + 1][cc] = bv.y;
            Bs[kg * 4 + 2][cc] = bv.z; Bs[kg * 4 + 3][cc] = bv.w;
        }
        __syncthreads();
#pragma unroll
        for (int kk = 0; kk < 16; kk++) {
            float a[8], bb[8];
            *(float4*)&a[0] = *(const float4*)&As[kk][ty * 8];
            *(float4*)&a[4] = *(const float4*)&As[kk][ty * 8 + 4];
            *(float4*)&bb[0] = *(const float4*)&Bs[kk][tx * 8];
            *(float4*)&bb[4] = *(const float4*)&Bs[kk][tx * 8 + 4];
#pragma unroll
            for (int i = 0; i < 8; i++)
#pragma unroll
                for (int j = 0; j < 8; j++) acc[i][j] = fmaf(a[i], bb[j], acc[i][j]);
        }
        __syncthreads();
    }

    const float gm = gamma[0];
#pragma unroll
    for (int i = 0; i < 8; i++) {
        int c = c0 + ty * 8 + i;
        float cf = g_coef[b * Cc + c];
        size_t obase = ((size_t)(b * Cc + c)) * Nn + m0 + tx * 8;
        float4 x0 = *(const float4*)(x + obase);
        float4 x1 = *(const float4*)(x + obase + 4);
        float4 o0, o1;
        o0.x = fmaf(gm, acc[i][0], cf * x0.x);
        o0.y = fmaf(gm, acc[i][1], cf * x0.y);
        o0.z = fmaf(gm, acc[i][2], cf * x0.z);
        o0.w = fmaf(gm, acc[i][3], cf * x0.w);
        o1.x = fmaf(gm, acc[i][4], cf * x1.x);
        o1.y = fmaf(gm, acc[i][5], cf * x1.y);
        o1.z = fmaf(gm, acc[i][6], cf * x1.z);
        o1.w = fmaf(gm, acc[i][7], cf * x1.w);
        *(float4*)(out + obase) = o0;
        *(float4*)(out + obase + 4) = o1;
    }
}

// ============================================================
extern "C" void kernel_launch(void* const* d_in, const int* in_sizes, int n_in,
                              void* d_out, int out_size) {
    const float* x     = (const float*)d_in[0];
    const float* Wq    = (const float*)d_in[1];
    const float* bq    = (const float*)d_in[2];
    const float* Wk    = (const float*)d_in[3];
    const float* bk    = (const float*)d_in[4];
    const float* Wv    = (const float*)d_in[5];
    const float* bv    = (const float*)d_in[6];
    const float* gamma = (const float*)d_in[7];
    const float* W1    = (const float*)d_in[8];
    const float* W2    = (const float*)d_in[9];
    const float* lamb  = (const float*)d_in[10];
    float* out = (float*)d_out;

    qk_kernel<<<dim3(Nn / 128, Bb), 128>>>(x, Wq, bq, Wk, bk);
    vproj_kernel<<<dim3(Nn / 128, Cc / 64, Bb), 128>>>(x, Wv, bv);
    score_kernel<<<dim3(Nn / 128, Nn / 64, Bb), 256>>>();
    softmax_kernel<<<Bb * Nn, 256>>>();
    stats_kernel<<<Bb * Cc, 256>>>(x);
    mlp_kernel<<<Bb, 256>>>(W1, W2, lamb);
    pv_kernel<<<dim3(Nn / 128, Cc / 128, Bb), 256>>>(x, gamma, out);
}

// round 2
// speedup vs baseline: 1.8736x; 1.8736x over previous
#include <cuda_runtime.h>
#include <math.h>
#include <stdint.h>

#define Bb 8
#define Cc 256
#define Nn 4096
#define Dd 32
#define Rr 32

// ---- scratch (__device__ globals: allowed; no runtime allocation) ----
__device__ float g_q[Bb * Nn * Dd];                 // [b][n][d]   4 MB
__device__ float g_k[Bb * Dd * Nn];                 // [b][d][n]   4 MB
__device__ float g_v[(size_t)Bb * Cc * Nn];         // [b][c][n]  32 MB
__device__ float g_attn[(size_t)Bb * Nn * Nn];      // [b][m][n] 512 MB
__device__ float g_stats[Bb * 2 * Cc];              // [b][mean(256),std(256)]
__device__ float g_coef[Bb * Cc];                   // 1 + lamb*sigmoid(...)

__device__ __forceinline__ uint32_t f2tf32(float x) {
    uint32_t r;
    asm("cvt.rna.tf32.f32 %0, %1;" : "=r"(r) : "f"(x));
    return r;
}

#define MMA_TF32(d, a, b2)                                                     \
    asm volatile(                                                              \
        "mma.sync.aligned.m16n8k8.row.col.f32.tf32.tf32.f32 "                  \
        "{%0,%1,%2,%3}, {%4,%5,%6,%7}, {%8,%9}, {%0,%1,%2,%3};"                \
        : "+f"(d[0]), "+f"(d[1]), "+f"(d[2]), "+f"(d[3])                       \
        : "r"(a[0]), "r"(a[1]), "r"(a[2]), "r"(a[3]), "r"(b2[0]), "r"(b2[1]))

// ============================================================
// Kernel 1: q[b,n,d] = sum_c Wq[d,c] x[b,c,n] + bq[d] ; same for k
// ============================================================
__global__ void qk_kernel(const float* __restrict__ x,
                          const float* __restrict__ Wq, const float* __restrict__ bq,
                          const float* __restrict__ Wk, const float* __restrict__ bk) {
    __shared__ float sWq[128][33];
    __shared__ float sWk[128][33];
    const int tid = threadIdx.x;
    const int b = blockIdx.y;
    const int n = blockIdx.x * 128 + tid;

    float accq[Dd], acck[Dd];
#pragma unroll
    for (int d = 0; d < Dd; d++) { accq[d] = bq[d]; acck[d] = bk[d]; }

    const float* xb = x + (size_t)b * Cc * Nn + n;

    for (int c0 = 0; c0 < Cc; c0 += 128) {
        __syncthreads();
        for (int i = tid; i < 128 * Dd; i += 128) {
            int d = i >> 7;
            int c = i & 127;
            sWq[c][d] = Wq[d * Cc + c0 + c];
            sWk[c][d] = Wk[d * Cc + c0 + c];
        }
        __syncthreads();
        for (int cc = 0; cc < 128; cc++) {
            float xv = xb[(size_t)(c0 + cc) * Nn];
#pragma unroll
            for (int d = 0; d < Dd; d++) {
                accq[d] = fmaf(sWq[cc][d], xv, accq[d]);
                acck[d] = fmaf(sWk[cc][d], xv, acck[d]);
            }
        }
    }
    float* qo = g_q + ((size_t)b * Nn + n) * Dd;
#pragma unroll
    for (int d = 0; d < Dd; d += 4)
        *(float4*)(qo + d) = make_float4(accq[d], accq[d + 1], accq[d + 2], accq[d + 3]);
    float* ko = g_k + (size_t)b * Dd * Nn + n;
#pragma unroll
    for (int d = 0; d < Dd; d++) ko[(size_t)d * Nn] = acck[d];
}

// ============================================================
// Kernel 2: v[b,c,n] = sum_c' Wv[c,c'] x[b,c',n] + bv[c]
// ============================================================
__global__ void vproj_kernel(const float* __restrict__ x,
                             const float* __restrict__ Wv, const float* __restrict__ bv) {
    __shared__ float sWv[64][65];
    const int tid = threadIdx.x;
    const int b = blockIdx.z;
    const int c0 = blockIdx.y * 64;
    const int n = blockIdx.x * 128 + tid;

    float acc[64];
#pragma unroll
    for (int i = 0; i < 64; i++) acc[i] = bv[c0 + i];

    const float* xb = x + (size_t)b * Cc * Nn + n;

    for (int cp0 = 0; cp0 < Cc; cp0 += 64) {
        __syncthreads();
        for (int t = tid; t < 64 * 64; t += 128) {
            int i = t >> 6;
            int j = t & 63;
            sWv[j][i] = Wv[(c0 + i) * Cc + cp0 + j];
        }
        __syncthreads();
        for (int j = 0; j < 64; j++) {
            float xv = xb[(size_t)(cp0 + j) * Nn];
#pragma unroll
            for (int i = 0; i < 64; i++) acc[i] = fmaf(sWv[j][i], xv, acc[i]);
        }
    }
    float* vo = g_v + ((size_t)b * Cc + c0) * Nn + n;
#pragma unroll
    for (int i = 0; i < 64; i++) vo[(size_t)i * Nn] = acc[i];
}

// ============================================================
// Kernel 3: S[b,m,n] = sum_d q[b,m,d] k[b,d,n]   (K = 32)
// ============================================================
__global__ void score_kernel() {
    __shared__ float sq[64][Dd];
    __shared__ float sk[Dd][128];
    const int tid = threadIdx.x;
    const int b = blockIdx.z;
    const int m0 = blockIdx.y * 64;
    const int n0 = blockIdx.x * 128;

    for (int i = tid; i < 64 * Dd; i += 256) {
        int m = i >> 5, d = i & 31;
        sq[m][d] = g_q[((size_t)b * Nn + m0 + m) * Dd + d];
    }
    for (int i = tid; i < Dd * 128; i += 256) {
        int d = i >> 7, n = i & 127;
        sk[d][n] = g_k[(size_t)b * Dd * Nn + (size_t)d * Nn + n0 + n];
    }
    __syncthreads();

    const int tx = tid & 15;
    const int ty = tid >> 4;
    float acc[4][8];
#pragma unroll
    for (int i = 0; i < 4; i++)
#pragma unroll
        for (int j = 0; j < 8; j++) acc[i][j] = 0.f;

#pragma unroll
    for (int d = 0; d < Dd; d++) {
        float qv[4];
#pragma unroll
        for (int i = 0; i < 4; i++) qv[i] = sq[ty * 4 + i][d];
        float kv[8];
        *(float4*)&kv[0] = *(const float4*)&sk[d][tx * 8];
        *(float4*)&kv[4] = *(const float4*)&sk[d][tx * 8 + 4];
#pragma unroll
        for (int i = 0; i < 4; i++)
#pragma unroll
            for (int j = 0; j < 8; j++) acc[i][j] = fmaf(qv[i], kv[j], acc[i][j]);
    }
#pragma unroll
    for (int i = 0; i < 4; i++) {
        float* o = g_attn + (size_t)b * Nn * Nn + (size_t)(m0 + ty * 4 + i) * Nn + n0 + tx * 8;
        *(float4*)&o[0] = make_float4(acc[i][0], acc[i][1], acc[i][2], acc[i][3]);
        *(float4*)&o[4] = make_float4(acc[i][4], acc[i][5], acc[i][6], acc[i][7]);
    }
}

// ============================================================
// Kernel 4: row softmax, float4-vectorized, one block per row
// ============================================================
__global__ void softmax_kernel() {
    __shared__ float4 buf[Nn / 4];
    __shared__ float red[8];
    const int tid = threadIdx.x;
    const int lane = tid & 31, warp = tid >> 5;
    float4* row = (float4*)(g_attn + (size_t)blockIdx.x * Nn);

    float m = -1e30f;
#pragma unroll
    for (int i = tid; i < Nn / 4; i += 256) {
        float4 v = row[i];
        buf[i] = v;
        m = fmaxf(m, fmaxf(fmaxf(v.x, v.y), fmaxf(v.z, v.w)));
    }
#pragma unroll
    for (int o = 16; o; o >>= 1) m = fmaxf(m, __shfl_xor_sync(0xffffffffu, m, o));
    if (lane == 0) red[warp] = m;
    __syncthreads();
    if (tid < 32) {
        float v = (tid < 8) ? red[tid] : -1e30f;
#pragma unroll
        for (int o = 4; o; o >>= 1) v = fmaxf(v, __shfl_xor_sync(0xffffffffu, v, o));
        if (tid == 0) red[0] = v;
    }
    __syncthreads();
    const float gmax = red[0];
    __syncthreads();

    float s = 0.f;
#pragma unroll
    for (int i = tid; i < Nn / 4; i += 256) {
        float4 v = buf[i];
        v.x = __expf(v.x - gmax);
        v.y = __expf(v.y - gmax);
        v.z = __expf(v.z - gmax);
        v.w = __expf(v.w - gmax);
        buf[i] = v;
        s += (v.x + v.y) + (v.z + v.w);
    }
#pragma unroll
    for (int o = 16; o; o >>= 1) s += __shfl_xor_sync(0xffffffffu, s, o);
    if (lane == 0) red[warp] = s;
    __syncthreads();
    if (tid < 32) {
        float v = (tid < 8) ? red[tid] : 0.f;
#pragma unroll
        for (int o = 4; o; o >>= 1) v += __shfl_xor_sync(0xffffffffu, v, o);
        if (tid == 0) red[0] = v;
    }
    __syncthreads();
    const float inv = 1.f / red[0];
#pragma unroll
    for (int i = tid; i < Nn / 4; i += 256) {
        float4 v = buf[i];
        v.x *= inv; v.y *= inv; v.z *= inv; v.w *= inv;
        row[i] = v;
    }
}

// ============================================================
// Kernel 5: per-(b,c) mean + unbiased std over N (float4)
// ============================================================
__global__ void stats_kernel(const float* __restrict__ x) {
    __shared__ float rs[8], rq[8];
    const int tid = threadIdx.x;
    const int lane = tid & 31, warp = tid >> 5;
    const float4* p = (const float4*)(x + (size_t)blockIdx.x * Nn);

    float s = 0.f, sq = 0.f;
#pragma unroll
    for (int i = tid; i < Nn / 4; i += 256) {
        float4 v = p[i];
        s += (v.x + v.y) + (v.z + v.w);
        sq = fmaf(v.x, v.x, sq); sq = fmaf(v.y, v.y, sq);
        sq = fmaf(v.z, v.z, sq); sq = fmaf(v.w, v.w, sq);
    }
#pragma unroll
    for (int o = 16; o; o >>= 1) {
        s += __shfl_xor_sync(0xffffffffu, s, o);
        sq += __shfl_xor_sync(0xffffffffu, sq, o);
    }
    if (lane == 0) { rs[warp] = s; rq[warp] = sq; }
    __syncthreads();
    if (tid == 0) {
        float ts = 0.f, tq = 0.f;
#pragma unroll
        for (int w = 0; w < 8; w++) { ts += rs[w]; tq += rq[w]; }
        float mean = ts / (float)Nn;
        float var = (tq - (float)Nn * mean * mean) / (float)(Nn - 1);
        float sd = sqrtf(fmaxf(var, 0.f));
        int b = blockIdx.x >> 8;
        int c = blockIdx.x & 255;
        g_stats[b * 2 * Cc + c] = mean;
        g_stats[b * 2 * Cc + Cc + c] = sd;
    }
}

// ============================================================
// Kernel 6: SE MLP -> coef[b,c] = 1 + lamb * sigmoid(relu(inp W1^T) W2^T)
// ============================================================
__global__ void mlp_kernel(const float* __restrict__ W1, const float* __restrict__ W2,
                           const float* __restrict__ lamb) {
    __shared__ float inp[2 * Cc];
    __shared__ float hid[Rr];
    const int tid = threadIdx.x;
    const int lane = tid & 31, warp = tid >> 5;
    const int b = blockIdx.x;

    for (int i = tid; i < 2 * Cc; i += 256) inp[i] = g_stats[b * 2 * Cc + i];
    __syncthreads();

#pragma unroll
    for (int t = 0; t < 4; t++) {
        int r = warp + 8 * t;
        float p = 0.f;
        for (int j = lane; j < 2 * Cc; j += 32) p = fmaf(inp[j], W1[r * 2 * Cc + j], p);
#pragma unroll
        for (int o = 16; o; o >>= 1) p += __shfl_xor_sync(0xffffffffu, p, o);
        if (lane == 0) hid[r] = fmaxf(p, 0.f);
    }
    __syncthreads();

    int c = tid;
    float s = 0.f;
#pragma unroll
    for (int r = 0; r < Rr; r++) s = fmaf(hid[r], W2[c * Rr + r], s);
    float a = 1.f / (1.f + __expf(-s));
    g_coef[b * Cc + c] = 1.f + lamb[0] * a;
}

// ============================================================
// Kernel 7 (tensor-core tf32): out[b,c,m] = gamma * (v @ attn^T) + coef*x
// 128(c) x 128(m) block tile, BK=32, 8 warps, mma.m16n8k8 tf32
// A = v[c][k] row-major, B = attn[m][k] ("col-major" k x n) — both native.
// ============================================================
__global__ void __launch_bounds__(256) pv_kernel(const float* __restrict__ x,
                                                 const float* __restrict__ gamma,
                                                 float* __restrict__ out) {
    __shared__ uint32_t As[128][36];   // [c][k] tf32, stride 36 -> frag loads conflict-free
    __shared__ uint32_t Bs[128][36];   // [m][k] tf32

    const int tid = threadIdx.x;
    const int lane = tid & 31;
    const int warp = tid >> 5;
    const int g = lane >> 2;          // 0..7
    const int tq = lane & 3;          // 0..3
    const int cw = (warp & 3) * 32;   // warp M offset (c)
    const int nw = (warp >> 2) * 64;  // warp N offset (m)

    const int b = blockIdx.z;
    const int c0 = blockIdx.y * 128;
    const int m0 = blockIdx.x * 128;

    const float* Ag = g_v + (size_t)b * Cc * Nn + (size_t)c0 * Nn;
    const float* Bg = g_attn + (size_t)b * Nn * Nn + (size_t)m0 * Nn;

    float acc[2][8][4];
#pragma unroll
    for (int mi = 0; mi < 2; mi++)
#pragma unroll
        for (int ni = 0; ni < 8; ni++)
#pragma unroll
            for (int j = 0; j < 4; j++) acc[mi][ni][j] = 0.f;

    float4 pa[4], pb[4];

    // prefetch chunk 0
#pragma unroll
    for (int i = 0; i < 4; i++) {
        int f = tid + i * 256;
        int r = f >> 3, kg = f & 7;
        pa[i] = *(const float4*)(Ag + (size_t)r * Nn + kg * 4);
        pb[i] = *(const float4*)(Bg + (size_t)r * Nn + kg * 4);
    }

    for (int k0 = 0; k0 < Nn; k0 += 32) {
        // store staged chunk to smem (tf32-rounded)
#pragma unroll
        for (int i = 0; i < 4; i++) {
            int f = tid + i * 256;
            int r = f >> 3, kg = f & 7;
            As[r][kg * 4 + 0] = f2tf32(pa[i].x);
            As[r][kg * 4 + 1] = f2tf32(pa[i].y);
            As[r][kg * 4 + 2] = f2tf32(pa[i].z);
            As[r][kg * 4 + 3] = f2tf32(pa[i].w);
            Bs[r][kg * 4 + 0] = f2tf32(pb[i].x);
            Bs[r][kg * 4 + 1] = f2tf32(pb[i].y);
            Bs[r][kg * 4 + 2] = f2tf32(pb[i].z);
            Bs[r][kg * 4 + 3] = f2tf32(pb[i].w);
        }
        __syncthreads();

        // prefetch next chunk while doing mma
        const bool more = (k0 + 32) < Nn;
        if (more) {
#pragma unroll
            for (int i = 0; i < 4; i++) {
                int f = tid + i * 256;
                int r = f >> 3, kg = f & 7;
                pa[i] = *(const float4*)(Ag + (size_t)r * Nn + k0 + 32 + kg * 4);
                pb[i] = *(const float4*)(Bg + (size_t)r * Nn + k0 + 32 + kg * 4);
            }
        }

#pragma unroll
        for (int ks = 0; ks < 4; ks++) {
            const int kk = ks * 8;
            uint32_t afr[2][4];
#pragma unroll
            for (int mi = 0; mi < 2; mi++) {
                int r = cw + mi * 16 + g;
                afr[mi][0] = As[r][kk + tq];
                afr[mi][1] = As[r + 8][kk + tq];
                afr[mi][2] = As[r][kk + tq + 4];
                afr[mi][3] = As[r + 8][kk + tq + 4];
            }
            uint32_t bfr[8][2];
#pragma unroll
            for (int ni = 0; ni < 8; ni++) {
                int r = nw + ni * 8 + g;
                bfr[ni][0] = Bs[r][kk + tq];
                bfr[ni][1] = Bs[r][kk + tq + 4];
            }
#pragma unroll
            for (int mi = 0; mi < 2; mi++)
#pragma unroll
                for (int ni = 0; ni < 8; ni++)
                    MMA_TF32(acc[mi][ni], afr[mi], bfr[ni]);
        }
        __syncthreads();
    }

    // epilogue: out = gamma*acc + coef*x
    const float gm = gamma[0];
#pragma unroll
    for (int mi = 0; mi < 2; mi++) {
#pragma unroll
        for (int half = 0; half < 2; half++) {
            int c = c0 + cw + mi * 16 + g + half * 8;
            float cf = g_coef[b * Cc + c];
            size_t ob = ((size_t)(b * Cc + c)) * Nn + m0;
#pragma unroll
            for (int ni = 0; ni < 8; ni++) {
                int m = nw + ni * 8 + 2 * tq;
                float2 xv = *(const float2*)(x + ob + m);
                float2 o;
                o.x = fmaf(gm, acc[mi][ni][half * 2 + 0], cf * xv.x);
                o.y = fmaf(gm, acc[mi][ni][half * 2 + 1], cf * xv.y);
                *(float2*)(out + ob + m) = o;
            }
        }
    }
}

// ============================================================
extern "C" void kernel_launch(void* const* d_in, const int* in_sizes, int n_in,
                              void* d_out, int out_size) {
    const float* x     = (const float*)d_in[0];
    const float* Wq    = (const float*)d_in[1];
    const float* bq    = (const float*)d_in[2];
    const float* Wk    = (const float*)d_in[3];
    const float* bk    = (const float*)d_in[4];
    const float* Wv    = (const float*)d_in[5];
    const float* bv    = (const float*)d_in[6];
    const float* gamma = (const float*)d_in[7];
    const float* W1    = (const float*)d_in[8];
    const float* W2    = (const float*)d_in[9];
    const float* lamb  = (const float*)d_in[10];
    float* out = (float*)d_out;

    qk_kernel<<<dim3(Nn / 128, Bb), 128>>>(x, Wq, bq, Wk, bk);
    vproj_kernel<<<dim3(Nn / 128, Cc / 64, Bb), 128>>>(x, Wv, bv);
    score_kernel<<<dim3(Nn / 128, Nn / 64, Bb), 256>>>();
    softmax_kernel<<<Bb * Nn, 256>>>();
    stats_kernel<<<Bb * Cc, 256>>>(x);
    mlp_kernel<<<Bb, 256>>>(W1, W2, lamb);
    pv_kernel<<<dim3(Nn / 128, Cc / 128, Bb), 256>>>(x, gamma, out);
}

// round 5
// speedup vs baseline: 2.0677x; 1.1036x over previous
#include <cuda_runtime.h>
#include <math.h>
#include <stdint.h>

#define Bb 8
#define Cc 256
#define Nn 4096
#define Dd 32
#define Rr 32

// ---- scratch (__device__ globals: allowed; no runtime allocation) ----
__device__ float g_q[Bb * Nn * Dd];                 // [b][n][d]   4 MB
__device__ float g_k[Bb * Dd * Nn];                 // [b][d][n]   4 MB
__device__ float g_v[(size_t)Bb * Cc * Nn];         // [b][c][n]  32 MB (tf32-rounded)
__device__ float g_attn[(size_t)Bb * Nn * Nn];      // [b][m][n] 512 MB  e=exp(s) tf32-rounded
__device__ float g_partial[(size_t)Bb * Nn * 32];   // per-row per-n-tile partial sums 4 MB
__device__ float g_rowinv[Bb * Nn];                 // 1/rowsum
__device__ float g_stats[Bb * 2 * Cc];
__device__ float g_coef[Bb * Cc];

__device__ __forceinline__ uint32_t f2tf32(float x) {
    uint32_t r;
    asm("cvt.rna.tf32.f32 %0, %1;" : "=r"(r) : "f"(x));
    return r;
}
__device__ __forceinline__ uint32_t sptr(const void* p) {
    return (uint32_t)__cvta_generic_to_shared(p);
}
__device__ __forceinline__ void cpa16(uint32_t d, const float* s) {
    asm volatile("cp.async.cg.shared.global [%0], [%1], 16;" :: "r"(d), "l"(s));
}
#define CP_COMMIT asm volatile("cp.async.commit_group;")
#define CP_WAIT1  asm volatile("cp.async.wait_group 1;")

#define MMA_TF32(d, a, b2)                                                     \
    asm volatile(                                                              \
        "mma.sync.aligned.m16n8k8.row.col.f32.tf32.tf32.f32 "                  \
        "{%0,%1,%2,%3}, {%4,%5,%6,%7}, {%8,%9}, {%0,%1,%2,%3};"                \
        : "+f"(d[0]), "+f"(d[1]), "+f"(d[2]), "+f"(d[3])                       \
        : "r"(a[0]), "r"(a[1]), "r"(a[2]), "r"(a[3]), "r"(b2[0]), "r"(b2[1]))

// ============================================================
// Kernel 1: q[b,n,d], k[b,d,n] projections
// ============================================================
__global__ void qk_kernel(const float* __restrict__ x,
                          const float* __restrict__ Wq, const float* __restrict__ bq,
                          const float* __restrict__ Wk, const float* __restrict__ bk) {
    __shared__ float sWq[128][33];
    __shared__ float sWk[128][33];
    const int tid = threadIdx.x;
    const int b = blockIdx.y;
    const int n = blockIdx.x * 128 + tid;

    float accq[Dd], acck[Dd];
#pragma unroll
    for (int d = 0; d < Dd; d++) { accq[d] = bq[d]; acck[d] = bk[d]; }

    const float* xb = x + (size_t)b * Cc * Nn + n;

    for (int c0 = 0; c0 < Cc; c0 += 128) {
        __syncthreads();
        for (int i = tid; i < 128 * Dd; i += 128) {
            int d = i >> 7;
            int c = i & 127;
            sWq[c][d] = Wq[d * Cc + c0 + c];
            sWk[c][d] = Wk[d * Cc + c0 + c];
        }
        __syncthreads();
        for (int cc = 0; cc < 128; cc++) {
            float xv = xb[(size_t)(c0 + cc) * Nn];
#pragma unroll
            for (int d = 0; d < Dd; d++) {
                accq[d] = fmaf(sWq[cc][d], xv, accq[d]);
                acck[d] = fmaf(sWk[cc][d], xv, acck[d]);
            }
        }
    }
    float* qo = g_q + ((size_t)b * Nn + n) * Dd;
#pragma unroll
    for (int d = 0; d < Dd; d += 4)
        *(float4*)(qo + d) = make_float4(accq[d], accq[d + 1], accq[d + 2], accq[d + 3]);
    float* ko = g_k + (size_t)b * Dd * Nn + n;
#pragma unroll
    for (int d = 0; d < Dd; d++) ko[(size_t)d * Nn] = acck[d];
}

// ============================================================
// Kernel 2: v projection (stores tf32-rounded)
// ============================================================
__global__ void vproj_kernel(const float* __restrict__ x,
                             const float* __restrict__ Wv, const float* __restrict__ bv) {
    __shared__ float sWv[64][65];
    const int tid = threadIdx.x;
    const int b = blockIdx.z;
    const int c0 = blockIdx.y * 64;
    const int n = blockIdx.x * 128 + tid;

    float acc[64];
#pragma unroll
    for (int i = 0; i < 64; i++) acc[i] = bv[c0 + i];

    const float* xb = x + (size_t)b * Cc * Nn + n;

    for (int cp0 = 0; cp0 < Cc; cp0 += 64) {
        __syncthreads();
        for (int t = tid; t < 64 * 64; t += 128) {
            int i = t >> 6;
            int j = t & 63;
            sWv[j][i] = Wv[(c0 + i) * Cc + cp0 + j];
        }
        __syncthreads();
        for (int j = 0; j < 64; j++) {
            float xv = xb[(size_t)(cp0 + j) * Nn];
#pragma unroll
            for (int i = 0; i < 64; i++) acc[i] = fmaf(sWv[j][i], xv, acc[i]);
        }
    }
    float* vo = g_v + ((size_t)b * Cc + c0) * Nn + n;
#pragma unroll
    for (int i = 0; i < 64; i++) vo[(size_t)i * Nn] = __uint_as_float(f2tf32(acc[i]));
}

// ============================================================
// Kernel 3: e[b,m,n] = exp(q.k)  (no max-sub; scores ~N(0,32), safe in fp32)
// writes tf32-rounded e + per-(row, n-tile) partial sums
// ============================================================
__global__ void score_kernel() {
    __shared__ float sq[64][33];
    __shared__ float sk[Dd][128];
    const int tid = threadIdx.x;
    const int b = blockIdx.z;
    const int m0 = blockIdx.y * 64;
    const int n0 = blockIdx.x * 128;

    for (int i = tid; i < 64 * Dd; i += 256) {
        int m = i >> 5, d = i & 31;
        sq[m][d] = g_q[((size_t)b * Nn + m0 + m) * Dd + d];
    }
    for (int i = tid; i < Dd * 128; i += 256) {
        int d = i >> 7, n = i & 127;
        sk[d][n] = g_k[(size_t)b * Dd * Nn + (size_t)d * Nn + n0 + n];
    }
    __syncthreads();

    const int tx = tid & 15;
    const int ty = tid >> 4;
    float acc[4][8];
#pragma unroll
    for (int i = 0; i < 4; i++)
#pragma unroll
        for (int j = 0; j < 8; j++) acc[i][j] = 0.f;

#pragma unroll
    for (int d = 0; d < Dd; d++) {
        float qv[4];
#pragma unroll
        for (int i = 0; i < 4; i++) qv[i] = sq[ty * 4 + i][d];
        float kv[8];
        *(float4*)&kv[0] = *(const float4*)&sk[d][tx * 8];
        *(float4*)&kv[4] = *(const float4*)&sk[d][tx * 8 + 4];
#pragma unroll
        for (int i = 0; i < 4; i++)
#pragma unroll
            for (int j = 0; j < 8; j++) acc[i][j] = fmaf(qv[i], kv[j], acc[i][j]);
    }

#pragma unroll
    for (int i = 0; i < 4; i++) {
        float e[8];
        float ps = 0.f;
#pragma unroll
        for (int j = 0; j < 8; j++) {
            float ev = __expf(acc[i][j]);
            e[j] = __uint_as_float(f2tf32(ev));   // round once; sum the SAME values
            ps += e[j];
        }
        float* o = g_attn + (size_t)b * Nn * Nn + (size_t)(m0 + ty * 4 + i) * Nn + n0 + tx * 8;
        *(float4*)&o[0] = make_float4(e[0], e[1], e[2], e[3]);
        *(float4*)&o[4] = make_float4(e[4], e[5], e[6], e[7]);
        // reduce partial over the 16 tx lanes (bits 0..3 of lane id)
#pragma unroll
        for (int off = 8; off; off >>= 1) ps += __shfl_xor_sync(0xffffffffu, ps, off);
        if (tx == 0)
            g_partial[((size_t)b * Nn + m0 + ty * 4 + i) * 32 + blockIdx.x] = ps;
    }
}

// ============================================================
// Kernel 3b: rowinv = 1/sum of 32 partials
// ============================================================
__global__ void inv_kernel() {
    int i = blockIdx.x * 256 + threadIdx.x;   // [0, Bb*Nn)
    const float4* p = (const float4*)g_partial + (size_t)i * 8;
    float s = 0.f;
#pragma unroll
    for (int t = 0; t < 8; t++) {
        float4 v = p[t];
        s += (v.x + v.y) + (v.z + v.w);
    }
    g_rowinv[i] = 1.f / s;
}

// ============================================================
// Kernel 4: per-(b,c) mean + unbiased std over N (float4)
// ============================================================
__global__ void stats_kernel(const float* __restrict__ x) {
    __shared__ float rs[8], rq[8];
    const int tid = threadIdx.x;
    const int lane = tid & 31, warp = tid >> 5;
    const float4* p = (const float4*)(x + (size_t)blockIdx.x * Nn);

    float s = 0.f, sq = 0.f;
#pragma unroll
    for (int i = tid; i < Nn / 4; i += 256) {
        float4 v = p[i];
        s += (v.x + v.y) + (v.z + v.w);
        sq = fmaf(v.x, v.x, sq); sq = fmaf(v.y, v.y, sq);
        sq = fmaf(v.z, v.z, sq); sq = fmaf(v.w, v.w, sq);
    }
#pragma unroll
    for (int o = 16; o; o >>= 1) {
        s += __shfl_xor_sync(0xffffffffu, s, o);
        sq += __shfl_xor_sync(0xffffffffu, sq, o);
    }
    if (lane == 0) { rs[warp] = s; rq[warp] = sq; }
    __syncthreads();
    if (tid == 0) {
        float ts = 0.f, tq = 0.f;
#pragma unroll
        for (int w = 0; w < 8; w++) { ts += rs[w]; tq += rq[w]; }
        float mean = ts / (float)Nn;
        float var = (tq - (float)Nn * mean * mean) / (float)(Nn - 1);
        float sd = sqrtf(fmaxf(var, 0.f));
        int b = blockIdx.x >> 8;
        int c = blockIdx.x & 255;
        g_stats[b * 2 * Cc + c] = mean;
        g_stats[b * 2 * Cc + Cc + c] = sd;
    }
}

// ============================================================
// Kernel 5: SE MLP -> coef[b,c]
// ============================================================
__global__ void mlp_kernel(const float* __restrict__ W1, const float* __restrict__ W2,
                           const float* __restrict__ lamb) {
    __shared__ float inp[2 * Cc];
    __shared__ float hid[Rr];
    const int tid = threadIdx.x;
    const int lane = tid & 31, warp = tid >> 5;
    const int b = blockIdx.x;

    for (int i = tid; i < 2 * Cc; i += 256) inp[i] = g_stats[b * 2 * Cc + i];
    __syncthreads();

#pragma unroll
    for (int t = 0; t < 4; t++) {
        int r = warp + 8 * t;
        float p = 0.f;
        for (int j = lane; j < 2 * Cc; j += 32) p = fmaf(inp[j], W1[r * 2 * Cc + j], p);
#pragma unroll
        for (int o = 16; o; o >>= 1) p += __shfl_xor_sync(0xffffffffu, p, o);
        if (lane == 0) hid[r] = fmaxf(p, 0.f);
    }
    __syncthreads();

    int c = tid;
    float s = 0.f;
#pragma unroll
    for (int r = 0; r < Rr; r++) s = fmaf(hid[r], W2[c * Rr + r], s);
    float a = 1.f / (1.f + __expf(-s));
    g_coef[b * Cc + c] = 1.f + lamb[0] * a;
}

// ============================================================
// Kernel 6 (tf32 MMA, cp.async 2-stage): out = gamma*rowinv[m]*(v @ e^T) + coef*x
// 128(c) x 128(m) tile, BK=16, 8 warps
// ============================================================
__global__ void __launch_bounds__(256) pv_kernel(const float* __restrict__ x,
                                                 const float* __restrict__ gamma,
                                                 float* __restrict__ out) {
    __shared__ float As[2][128][20];   // [c][k], pad 20 -> conflict-free frag loads
    __shared__ float Bs[2][128][20];   // [m][k]

    const int tid = threadIdx.x;
    const int lane = tid & 31;
    const int warp = tid >> 5;
    const int g = lane >> 2;
    const int tq = lane & 3;
    const int cw = (warp & 3) * 32;
    const int nw = (warp >> 2) * 64;

    const int b = blockIdx.z;
    const int c0 = blockIdx.y * 128;
    const int m0 = blockIdx.x * 128;

    const float* Ag = g_v + (size_t)b * Cc * Nn + (size_t)c0 * Nn;
    const float* Bg = g_attn + (size_t)b * Nn * Nn + (size_t)m0 * Nn;

    float acc[2][8][4];
#pragma unroll
    for (int mi = 0; mi < 2; mi++)
#pragma unroll
        for (int ni = 0; ni < 8; ni++)
#pragma unroll
            for (int j = 0; j < 4; j++) acc[mi][ni][j] = 0.f;

    const int r0 = tid >> 2;           // 0..63 (thread's row for loads, 2 rows apart)
    const int kg = tid & 3;            // float4 group

    // stage loader: 2 float4s per matrix per thread (rows r0 and r0+64)
#define ISSUE_STAGE(bufi, kk0)                                                  \
    do {                                                                        \
        cpa16(sptr(&As[bufi][r0][kg * 4]), Ag + (size_t)r0 * Nn + (kk0) + kg * 4);          \
        cpa16(sptr(&As[bufi][r0 + 64][kg * 4]), Ag + (size_t)(r0 + 64) * Nn + (kk0) + kg * 4); \
        cpa16(sptr(&Bs[bufi][r0][kg * 4]), Bg + (size_t)r0 * Nn + (kk0) + kg * 4);          \
        cpa16(sptr(&Bs[bufi][r0 + 64][kg * 4]), Bg + (size_t)(r0 + 64) * Nn + (kk0) + kg * 4); \
        CP_COMMIT;                                                              \
    } while (0)

    ISSUE_STAGE(0, 0);
    ISSUE_STAGE(1, 16);

    const int ITERS = Nn / 16;         // 256
    for (int it = 0; it < ITERS; it++) {
        CP_WAIT1;
        __syncthreads();
        const float (*A_)[20] = As[it & 1];
        const float (*B_)[20] = Bs[it & 1];
#pragma unroll
        for (int ks = 0; ks < 2; ks++) {
            const int kk = ks * 8;
            uint32_t afr[2][4];
#pragma unroll
            for (int mi = 0; mi < 2; mi++) {
                int r = cw + mi * 16 + g;
                afr[mi][0] = __float_as_uint(A_[r][kk + tq]);
                afr[mi][1] = __float_as_uint(A_[r + 8][kk + tq]);
                afr[mi][2] = __float_as_uint(A_[r][kk + tq + 4]);
                afr[mi][3] = __float_as_uint(A_[r + 8][kk + tq + 4]);
            }
            uint32_t bfr[8][2];
#pragma unroll
            for (int ni = 0; ni < 8; ni++) {
                int r = nw + ni * 8 + g;
                bfr[ni][0] = __float_as_uint(B_[r][kk + tq]);
                bfr[ni][1] = __float_as_uint(B_[r][kk + tq + 4]);
            }
#pragma unroll
            for (int mi = 0; mi < 2; mi++)
#pragma unroll
                for (int ni = 0; ni < 8; ni++)
                    MMA_TF32(acc[mi][ni], afr[mi], bfr[ni]);
        }
        __syncthreads();
        if (it + 2 < ITERS) {
            ISSUE_STAGE(it & 1, (it + 2) * 16);
        } else {
            CP_COMMIT;   // empty group keeps wait_group accounting correct
        }
    }

    // epilogue: out = gamma * rowinv[m] * acc + coef * x
    const float gm = gamma[0];
    const float* inv = g_rowinv + (size_t)b * Nn + m0;
#pragma unroll
    for (int mi = 0; mi < 2; mi++) {
#pragma unroll
        for (int half = 0; half < 2; half++) {
            int c = c0 + cw + mi * 16 + g + half * 8;
            float cf = g_coef[b * Cc + c];
            size_t ob = ((size_t)(b * Cc + c)) * Nn + m0;
#pragma unroll
            for (int ni = 0; ni < 8; ni++) {
                int m = nw + ni * 8 + 2 * tq;
                float2 iv = *(const float2*)(inv + m);
                float2 xv = *(const float2*)(x + ob + m);
                float2 o;
                o.x = fmaf(gm * iv.x, acc[mi][ni][half * 2 + 0], cf * xv.x);
                o.y = fmaf(gm * iv.y, acc[mi][ni][half * 2 + 1], cf * xv.y);
                *(float2*)(out + ob + m) = o;
            }
        }
    }
}

// ============================================================
extern "C" void kernel_launch(void* const* d_in, const int* in_sizes, int n_in,
                              void* d_out, int out_size) {
    const float* x     = (const float*)d_in[0];
    const float* Wq    = (const float*)d_in[1];
    const float* bq    = (const float*)d_in[2];
    const float* Wk    = (const float*)d_in[3];
    const float* bk    = (const float*)d_in[4];
    const float* Wv    = (const float*)d_in[5];
    const float* bv    = (const float*)d_in[6];
    const float* gamma = (const float*)d_in[7];
    const float* W1    = (const float*)d_in[8];
    const float* W2    = (const float*)d_in[9];
    const float* lamb  = (const float*)d_in[10];
    float* out = (float*)d_out;

    qk_kernel<<<dim3(Nn / 128, Bb), 128>>>(x, Wq, bq, Wk, bk);
    vproj_kernel<<<dim3(Nn / 128, Cc / 64, Bb), 128>>>(x, Wv, bv);
    score_kernel<<<dim3(Nn / 128, Nn / 64, Bb), 256>>>();
    inv_kernel<<<Bb * Nn / 256, 256>>>();
    stats_kernel<<<Bb * Cc, 256>>>(x);
    mlp_kernel<<<Bb, 256>>>(W1, W2, lamb);
    pv_kernel<<<dim3(Nn / 128, Cc / 128, Bb), 256>>>(x, gamma, out);
}

// round 6
// speedup vs baseline: 2.1312x; 1.0307x over previous
#include <cuda_runtime.h>
#include <math.h>
#include <stdint.h>

#define Bb 8
#define Cc 256
#define Nn 4096
#define Dd 32
#define Rr 32

// ---- scratch ----
__device__ float g_q[Bb * Nn * Dd];                 // [b][n][d]
__device__ float g_k[Bb * Dd * Nn];                 // [b][d][n]
__device__ float g_v[(size_t)Bb * Cc * Nn];         // [b][c][n] tf32-rounded
__device__ float g_attn[(size_t)Bb * Nn * Nn];      // e=exp(s) tf32-rounded
__device__ float g_partial[(size_t)Bb * Nn * 64];   // per-(row, n-tile, n-warp) sums
__device__ float g_rowinv[Bb * Nn];
__device__ float g_stats[Bb * 2 * Cc];
__device__ float g_coef[Bb * Cc];

__device__ __forceinline__ uint32_t f2tf32(float x) {
    uint32_t r;
    asm("cvt.rna.tf32.f32 %0, %1;" : "=r"(r) : "f"(x));
    return r;
}
__device__ __forceinline__ float tf32f(float x) { return __uint_as_float(f2tf32(x)); }
__device__ __forceinline__ uint32_t sptr(const void* p) {
    return (uint32_t)__cvta_generic_to_shared(p);
}
__device__ __forceinline__ void cpa16(uint32_t d, const float* s) {
    asm volatile("cp.async.cg.shared.global [%0], [%1], 16;" :: "r"(d), "l"(s));
}
#define CP_COMMIT asm volatile("cp.async.commit_group;")
#define CP_WAIT1  asm volatile("cp.async.wait_group 1;")

#define MMA_TF32(d, a, b2)                                                     \
    asm volatile(                                                              \
        "mma.sync.aligned.m16n8k8.row.col.f32.tf32.tf32.f32 "                  \
        "{%0,%1,%2,%3}, {%4,%5,%6,%7}, {%8,%9}, {%0,%1,%2,%3};"                \
        : "+f"(d[0]), "+f"(d[1]), "+f"(d[2]), "+f"(d[3])                       \
        : "r"(a[0]), "r"(a[1]), "r"(a[2]), "r"(a[3]), "r"(b2[0]), "r"(b2[1]))

// ============================================================
// Kernel 1: q[b,n,d], k[b,d,n] projections (float4 smem reads)
// ============================================================
__global__ void qk_kernel(const float* __restrict__ x,
                          const float* __restrict__ Wq, const float* __restrict__ bq,
                          const float* __restrict__ Wk, const float* __restrict__ bk) {
    __shared__ float sWq[128 * 36];   // [c][d] stride 36 (16B-aligned rows)
    __shared__ float sWk[128 * 36];
    const int tid = threadIdx.x;
    const int b = blockIdx.y;
    const int n = blockIdx.x * 128 + tid;

    float accq[Dd], acck[Dd];
#pragma unroll
    for (int d = 0; d < Dd; d++) { accq[d] = bq[d]; acck[d] = bk[d]; }

    const float* xb = x + (size_t)b * Cc * Nn + n;

    for (int c0 = 0; c0 < Cc; c0 += 128) {
        __syncthreads();
        for (int i = tid; i < 128 * Dd; i += 128) {
            int d = i >> 7;
            int c = i & 127;
            sWq[c * 36 + d] = Wq[d * Cc + c0 + c];
            sWk[c * 36 + d] = Wk[d * Cc + c0 + c];
        }
        __syncthreads();
        for (int cc = 0; cc < 128; cc++) {
            float xv = xb[(size_t)(c0 + cc) * Nn];
            const float4* wq4 = (const float4*)(sWq + cc * 36);
            const float4* wk4 = (const float4*)(sWk + cc * 36);
#pragma unroll
            for (int d4 = 0; d4 < 8; d4++) {
                float4 wq = wq4[d4];
                float4 wk = wk4[d4];
                accq[d4 * 4 + 0] = fmaf(wq.x, xv, accq[d4 * 4 + 0]);
                accq[d4 * 4 + 1] = fmaf(wq.y, xv, accq[d4 * 4 + 1]);
                accq[d4 * 4 + 2] = fmaf(wq.z, xv, accq[d4 * 4 + 2]);
                accq[d4 * 4 + 3] = fmaf(wq.w, xv, accq[d4 * 4 + 3]);
                acck[d4 * 4 + 0] = fmaf(wk.x, xv, acck[d4 * 4 + 0]);
                acck[d4 * 4 + 1] = fmaf(wk.y, xv, acck[d4 * 4 + 1]);
                acck[d4 * 4 + 2] = fmaf(wk.z, xv, acck[d4 * 4 + 2]);
                acck[d4 * 4 + 3] = fmaf(wk.w, xv, acck[d4 * 4 + 3]);
            }
        }
    }
    float* qo = g_q + ((size_t)b * Nn + n) * Dd;
#pragma unroll
    for (int d = 0; d < Dd; d += 4)
        *(float4*)(qo + d) = make_float4(accq[d], accq[d + 1], accq[d + 2], accq[d + 3]);
    float* ko = g_k + (size_t)b * Dd * Nn + n;
#pragma unroll
    for (int d = 0; d < Dd; d++) ko[(size_t)d * Nn] = acck[d];
}

// ============================================================
// Kernel 2: v projection (float4 smem reads, stores tf32-rounded)
// ============================================================
__global__ void vproj_kernel(const float* __restrict__ x,
                             const float* __restrict__ Wv, const float* __restrict__ bv) {
    __shared__ float sWv[64 * 68];    // [c'][c] stride 68 (16B-aligned rows)
    const int tid = threadIdx.x;
    const int b = blockIdx.z;
    const int c0 = blockIdx.y * 64;
    const int n = blockIdx.x * 128 + tid;

    float acc[64];
#pragma unroll
    for (int i = 0; i < 64; i++) acc[i] = bv[c0 + i];

    const float* xb = x + (size_t)b * Cc * Nn + n;

    for (int cp0 = 0; cp0 < Cc; cp0 += 64) {
        __syncthreads();
        for (int t = tid; t < 64 * 64; t += 128) {
            int i = t >> 6;      // c
            int j = t & 63;      // c'
            sWv[j * 68 + i] = Wv[(c0 + i) * Cc + cp0 + j];
        }
        __syncthreads();
        for (int j = 0; j < 64; j++) {
            float xv = xb[(size_t)(cp0 + j) * Nn];
            const float4* w4 = (const float4*)(sWv + j * 68);
#pragma unroll
            for (int i4 = 0; i4 < 16; i4++) {
                float4 w = w4[i4];
                acc[i4 * 4 + 0] = fmaf(w.x, xv, acc[i4 * 4 + 0]);
                acc[i4 * 4 + 1] = fmaf(w.y, xv, acc[i4 * 4 + 1]);
                acc[i4 * 4 + 2] = fmaf(w.z, xv, acc[i4 * 4 + 2]);
                acc[i4 * 4 + 3] = fmaf(w.w, xv, acc[i4 * 4 + 3]);
            }
        }
    }
    float* vo = g_v + ((size_t)b * Cc + c0) * Nn + n;
#pragma unroll
    for (int i = 0; i < 64; i++) vo[(size_t)i * Nn] = tf32f(acc[i]);
}

// ============================================================
// Kernel 3: e = exp(q.k) via 3xTF32 MMA. 128m x 128n tile, 8 warps.
// dynamic smem: qh/ql [128][36], kh/kl [128][36] (k stored [n][d])
// ============================================================
__global__ void __launch_bounds__(256) score_kernel() {
    extern __shared__ float sm[];
    float* qh = sm;
    float* ql = sm + 128 * 36;
    float* kh = sm + 2 * 128 * 36;
    float* kl = sm + 3 * 128 * 36;

    const int tid = threadIdx.x;
    const int lane = tid & 31;
    const int warp = tid >> 5;
    const int g = lane >> 2;
    const int tq = lane & 3;
    const int cw = (warp & 3) * 32;   // m offset of warp
    const int nw = (warp >> 2) * 64;  // n offset of warp

    const int b = blockIdx.z;
    const int m0 = blockIdx.y * 128;
    const int n0 = blockIdx.x * 128;

    // fill q (hi/lo split)
    for (int i = tid; i < 128 * 8; i += 256) {
        int m = i >> 3, dg = i & 7;
        float4 v = *(const float4*)(g_q + ((size_t)b * Nn + m0 + m) * Dd + dg * 4);
        float h0 = tf32f(v.x), h1 = tf32f(v.y), h2 = tf32f(v.z), h3 = tf32f(v.w);
        float* ph = qh + m * 36 + dg * 4;
        float* pl = ql + m * 36 + dg * 4;
        ph[0] = h0; ph[1] = h1; ph[2] = h2; ph[3] = h3;
        pl[0] = tf32f(v.x - h0); pl[1] = tf32f(v.y - h1);
        pl[2] = tf32f(v.z - h2); pl[3] = tf32f(v.w - h3);
    }
    // fill k transposed [n][d]
    for (int i = tid; i < Dd * 128; i += 256) {
        int d = i >> 7, n = i & 127;
        float v = g_k[((size_t)b * Dd + d) * Nn + n0 + n];
        float h = tf32f(v);
        kh[n * 36 + d] = h;
        kl[n * 36 + d] = tf32f(v - h);
    }
    __syncthreads();

    float acc[2][8][4];
#pragma unroll
    for (int mi = 0; mi < 2; mi++)
#pragma unroll
        for (int ni = 0; ni < 8; ni++)
#pragma unroll
            for (int j = 0; j < 4; j++) acc[mi][ni][j] = 0.f;

#pragma unroll
    for (int ks = 0; ks < 4; ks++) {
        const int kk = ks * 8;
        uint32_t ah[2][4], al[2][4];
#pragma unroll
        for (int mi = 0; mi < 2; mi++) {
            int r = cw + mi * 16 + g;
            ah[mi][0] = __float_as_uint(qh[r * 36 + kk + tq]);
            ah[mi][1] = __float_as_uint(qh[(r + 8) * 36 + kk + tq]);
            ah[mi][2] = __float_as_uint(qh[r * 36 + kk + tq + 4]);
            ah[mi][3] = __float_as_uint(qh[(r + 8) * 36 + kk + tq + 4]);
            al[mi][0] = __float_as_uint(ql[r * 36 + kk + tq]);
            al[mi][1] = __float_as_uint(ql[(r + 8) * 36 + kk + tq]);
            al[mi][2] = __float_as_uint(ql[r * 36 + kk + tq + 4]);
            al[mi][3] = __float_as_uint(ql[(r + 8) * 36 + kk + tq + 4]);
        }
        uint32_t bh[8][2], bl[8][2];
#pragma unroll
        for (int ni = 0; ni < 8; ni++) {
            int r = nw + ni * 8 + g;
            bh[ni][0] = __float_as_uint(kh[r * 36 + kk + tq]);
            bh[ni][1] = __float_as_uint(kh[r * 36 + kk + tq + 4]);
            bl[ni][0] = __float_as_uint(kl[r * 36 + kk + tq]);
            bl[ni][1] = __float_as_uint(kl[r * 36 + kk + tq + 4]);
        }
#pragma unroll
        for (int mi = 0; mi < 2; mi++)
#pragma unroll
            for (int ni = 0; ni < 8; ni++) {
                MMA_TF32(acc[mi][ni], ah[mi], bl[ni]);
                MMA_TF32(acc[mi][ni], al[mi], bh[ni]);
                MMA_TF32(acc[mi][ni], ah[mi], bh[ni]);
            }
    }

    // epilogue: e = tf32(exp(s)), store + per-(row, warp) partial sums
#pragma unroll
    for (int mi = 0; mi < 2; mi++) {
#pragma unroll
        for (int half = 0; half < 2; half++) {
            const int m = m0 + cw + mi * 16 + g + half * 8;
            float2 vals[8];
            float ps = 0.f;
#pragma unroll
            for (int ni = 0; ni < 8; ni++) {
                float e0 = tf32f(__expf(acc[mi][ni][half * 2 + 0]));
                float e1 = tf32f(__expf(acc[mi][ni][half * 2 + 1]));
                vals[ni] = make_float2(e0, e1);
                ps += e0 + e1;
            }
            float* row = g_attn + (size_t)b * Nn * Nn + (size_t)m * Nn + n0 + nw + 2 * tq;
#pragma unroll
            for (int ni = 0; ni < 8; ni++) *(float2*)(row + ni * 8) = vals[ni];
            ps += __shfl_xor_sync(0xffffffffu, ps, 1);
            ps += __shfl_xor_sync(0xffffffffu, ps, 2);
            if (tq == 0)
                g_partial[((size_t)b * Nn + m) * 64 + blockIdx.x * 2 + (warp >> 2)] = ps;
        }
    }
}

// ============================================================
// Kernel 3b: rowinv = 1/sum of 64 partials
// ============================================================
__global__ void inv_kernel() {
    int i = blockIdx.x * 256 + threadIdx.x;   // [0, Bb*Nn)
    const float4* p = (const float4*)g_partial + (size_t)i * 16;
    float s = 0.f;
#pragma unroll
    for (int t = 0; t < 16; t++) {
        float4 v = p[t];
        s += (v.x + v.y) + (v.z + v.w);
    }
    g_rowinv[i] = 1.f / s;
}

// ============================================================
// Kernel 4: per-(b,c) mean + unbiased std
// ============================================================
__global__ void stats_kernel(const float* __restrict__ x) {
    __shared__ float rs[8], rq[8];
    const int tid = threadIdx.x;
    const int lane = tid & 31, warp = tid >> 5;
    const float4* p = (const float4*)(x + (size_t)blockIdx.x * Nn);

    float s = 0.f, sq = 0.f;
#pragma unroll
    for (int i = tid; i < Nn / 4; i += 256) {
        float4 v = p[i];
        s += (v.x + v.y) + (v.z + v.w);
        sq = fmaf(v.x, v.x, sq); sq = fmaf(v.y, v.y, sq);
        sq = fmaf(v.z, v.z, sq); sq = fmaf(v.w, v.w, sq);
    }
#pragma unroll
    for (int o = 16; o; o >>= 1) {
        s += __shfl_xor_sync(0xffffffffu, s, o);
        sq += __shfl_xor_sync(0xffffffffu, sq, o);
    }
    if (lane == 0) { rs[warp] = s; rq[warp] = sq; }
    __syncthreads();
    if (tid == 0) {
        float ts = 0.f, tq = 0.f;
#pragma unroll
        for (int w = 0; w < 8; w++) { ts += rs[w]; tq += rq[w]; }
        float mean = ts / (float)Nn;
        float var = (tq - (float)Nn * mean * mean) / (float)(Nn - 1);
        float sd = sqrtf(fmaxf(var, 0.f));
        int b = blockIdx.x >> 8;
        int c = blockIdx.x & 255;
        g_stats[b * 2 * Cc + c] = mean;
        g_stats[b * 2 * Cc + Cc + c] = sd;
    }
}

// ============================================================
// Kernel 5: SE MLP -> coef[b,c]
// ============================================================
__global__ void mlp_kernel(const float* __restrict__ W1, const float* __restrict__ W2,
                           const float* __restrict__ lamb) {
    __shared__ float inp[2 * Cc];
    __shared__ float hid[Rr];
    const int tid = threadIdx.x;
    const int lane = tid & 31, warp = tid >> 5;
    const int b = blockIdx.x;

    for (int i = tid; i < 2 * Cc; i += 256) inp[i] = g_stats[b * 2 * Cc + i];
    __syncthreads();

#pragma unroll
    for (int t = 0; t < 4; t++) {
        int r = warp + 8 * t;
        float p = 0.f;
        for (int j = lane; j < 2 * Cc; j += 32) p = fmaf(inp[j], W1[r * 2 * Cc + j], p);
#pragma unroll
        for (int o = 16; o; o >>= 1) p += __shfl_xor_sync(0xffffffffu, p, o);
        if (lane == 0) hid[r] = fmaxf(p, 0.f);
    }
    __syncthreads();

    int c = tid;
    float s = 0.f;
#pragma unroll
    for (int r = 0; r < Rr; r++) s = fmaf(hid[r], W2[c * Rr + r], s);
    float a = 1.f / (1.f + __expf(-s));
    g_coef[b * Cc + c] = 1.f + lamb[0] * a;
}

// ============================================================
// Kernel 6: out = gamma*rowinv[m]*(v @ e^T) + coef*x
// 128x128 tile, BK=16, 3-stage cp.async, 8 warps. Dynamic smem.
// grid = (2 c-tiles, 32 m-tiles, 8 b): c-pair adjacent -> attn L2 reuse
// ============================================================
__global__ void __launch_bounds__(256) pv_kernel(const float* __restrict__ x,
                                                 const float* __restrict__ gamma,
                                                 float* __restrict__ out) {
    extern __shared__ float sm[];
    float* sAs = sm;                        // [3][128][20]
    float* sBs = sm + 3 * 128 * 20;         // [3][128][20]

    const int tid = threadIdx.x;
    const int lane = tid & 31;
    const int warp = tid >> 5;
    const int g = lane >> 2;
    const int tq = lane & 3;
    const int cw = (warp & 3) * 32;
    const int nw = (warp >> 2) * 64;

    const int b = blockIdx.z;
    const int c0 = blockIdx.x * 128;
    const int m0 = blockIdx.y * 128;

    const float* Ag = g_v + (size_t)b * Cc * Nn + (size_t)c0 * Nn;
    const float* Bg = g_attn + (size_t)b * Nn * Nn + (size_t)m0 * Nn;

    float acc[2][8][4];
#pragma unroll
    for (int mi = 0; mi < 2; mi++)
#pragma unroll
        for (int ni = 0; ni < 8; ni++)
#pragma unroll
            for (int j = 0; j < 4; j++) acc[mi][ni][j] = 0.f;

    const int r0 = tid >> 2;           // 0..63
    const int kg = tid & 3;

#define ISSUE_STAGE(bufi, kk0)                                                        \
    do {                                                                              \
        cpa16(sptr(&sAs[(((bufi) * 128) + r0) * 20 + kg * 4]),                        \
              Ag + (size_t)r0 * Nn + (kk0) + kg * 4);                                 \
        cpa16(sptr(&sAs[(((bufi) * 128) + r0 + 64) * 20 + kg * 4]),                   \
              Ag + (size_t)(r0 + 64) * Nn + (kk0) + kg * 4);                          \
        cpa16(sptr(&sBs[(((bufi) * 128) + r0) * 20 + kg * 4]),                        \
              Bg + (size_t)r0 * Nn + (kk0) + kg * 4);                                 \
        cpa16(sptr(&sBs[(((bufi) * 128) + r0 + 64) * 20 + kg * 4]),                   \
              Bg + (size_t)(r0 + 64) * Nn + (kk0) + kg * 4);                          \
        CP_COMMIT;                                                                    \
    } while (0)

    ISSUE_STAGE(0, 0);
    ISSUE_STAGE(1, 16);

    const int ITERS = Nn / 16;         // 256
    int buf = 0;
    for (int it = 0; it < ITERS; it++) {
        CP_WAIT1;
        __syncthreads();
        const float* A_ = sAs + buf * 128 * 20;
        const float* B_ = sBs + buf * 128 * 20;
#pragma unroll
        for (int ks = 0; ks < 2; ks++) {
            const int kk = ks * 8;
            uint32_t afr[2][4];
#pragma unroll
            for (int mi = 0; mi < 2; mi++) {
                int r = cw + mi * 16 + g;
                afr[mi][0] = __float_as_uint(A_[r * 20 + kk + tq]);
                afr[mi][1] = __float_as_uint(A_[(r + 8) * 20 + kk + tq]);
                afr[mi][2] = __float_as_uint(A_[r * 20 + kk + tq + 4]);
                afr[mi][3] = __float_as_uint(A_[(r + 8) * 20 + kk + tq + 4]);
            }
            uint32_t bfr[8][2];
#pragma unroll
            for (int ni = 0; ni < 8; ni++) {
                int r = nw + ni * 8 + g;
                bfr[ni][0] = __float_as_uint(B_[r * 20 + kk + tq]);
                bfr[ni][1] = __float_as_uint(B_[r * 20 + kk + tq + 4]);
            }
#pragma unroll
            for (int mi = 0; mi < 2; mi++)
#pragma unroll
                for (int ni = 0; ni < 8; ni++)
                    MMA_TF32(acc[mi][ni], afr[mi], bfr[ni]);
        }
        __syncthreads();
        if (it + 2 < ITERS) {
            int nb = buf + 2; if (nb >= 3) nb -= 3;
            ISSUE_STAGE(nb, (it + 2) * 16);
        } else {
            CP_COMMIT;   // keep group accounting so CP_WAIT1 drains the tail
        }
        buf++; if (buf == 3) buf = 0;
    }

    const float gm = gamma[0];
    const float* inv = g_rowinv + (size_t)b * Nn + m0;
#pragma unroll
    for (int mi = 0; mi < 2; mi++) {
#pragma unroll
        for (int half = 0; half < 2; half++) {
            int c = c0 + cw + mi * 16 + g + half * 8;
            float cf = g_coef[b * Cc + c];
            size_t ob = ((size_t)(b * Cc + c)) * Nn + m0;
#pragma unroll
            for (int ni = 0; ni < 8; ni++) {
                int m = nw + ni * 8 + 2 * tq;
                float2 iv = *(const float2*)(inv + m);
                float2 xv = *(const float2*)(x + ob + m);
                float2 o;
                o.x = fmaf(gm * iv.x, acc[mi][ni][half * 2 + 0], cf * xv.x);
                o.y = fmaf(gm * iv.y, acc[mi][ni][half * 2 + 1], cf * xv.y);
                *(float2*)(out + ob + m) = o;
            }
        }
    }
}

// ============================================================
extern "C" void kernel_launch(void* const* d_in, const int* in_sizes, int n_in,
                              void* d_out, int out_size) {
    const float* x     = (const float*)d_in[0];
    const float* Wq    = (const float*)d_in[1];
    const float* bq    = (const float*)d_in[2];
    const float* Wk    = (const float*)d_in[3];
    const float* bk    = (const float*)d_in[4];
    const float* Wv    = (const float*)d_in[5];
    const float* bv    = (const float*)d_in[6];
    const float* gamma = (const float*)d_in[7];
    const float* W1    = (const float*)d_in[8];
    const float* W2    = (const float*)d_in[9];
    const float* lamb  = (const float*)d_in[10];
    float* out = (float*)d_out;

    const int SCORE_SMEM = 4 * 128 * 36 * 4;       // 73728 B
    const int PV_SMEM    = 6 * 128 * 20 * 4;       // 61440 B
    cudaFuncSetAttribute(score_kernel, cudaFuncAttributeMaxDynamicSharedMemorySize, SCORE_SMEM);
    cudaFuncSetAttribute(pv_kernel, cudaFuncAttributeMaxDynamicSharedMemorySize, PV_SMEM);

    qk_kernel<<<dim3(Nn / 128, Bb), 128>>>(x, Wq, bq, Wk, bk);
    vproj_kernel<<<dim3(Nn / 128, Cc / 64, Bb), 128>>>(x, Wv, bv);
    score_kernel<<<dim3(Nn / 128, Nn / 128, Bb), 256, SCORE_SMEM>>>();
    inv_kernel<<<Bb * Nn / 256, 256>>>();
    stats_kernel<<<Bb * Cc, 256>>>(x);
    mlp_kernel<<<Bb, 256>>>(W1, W2, lamb);
    pv_kernel<<<dim3(Cc / 128, Nn / 128, Bb), 256, PV_SMEM>>>(x, gamma, out);
}